// round 1
// baseline (speedup 1.0000x reference)
#include <cuda_runtime.h>
#include <cstdint>

#define NN  50000
#define EE  800000
#define FIN 128
#define KK  32

// ---------------- device scratch (no allocations allowed) ----------------
__device__ float g_xs[(size_t)NN * FIN];    // dense MaxK-sparsified features
__device__ float g_agg[(size_t)NN * FIN];   // normalized neighbor aggregate
__device__ int   g_deg[NN];
__device__ int   g_off[NN + 1];
__device__ int   g_cur[NN];
__device__ int   g_csr[EE];                 // src ids grouped by dst

// ---------------- kernels ----------------

__global__ void init_kernel() {
    int i = blockIdx.x * blockDim.x + threadIdx.x;
    if (i < NN) { g_deg[i] = 0; g_cur[i] = 0; }
}

__global__ void deg_kernel(const int* __restrict__ dst) {
    int e = blockIdx.x * blockDim.x + threadIdx.x;
    if (e < EE) atomicAdd(&g_deg[dst[e]], 1);
}

// single-block exclusive scan of g_deg -> g_off (warp-shuffle based)
__global__ void scan_kernel() {
    __shared__ int warpsums[32];
    __shared__ int s_carry, s_tot;
    int t = threadIdx.x, lane = t & 31, wid = t >> 5;
    if (t == 0) s_carry = 0;
    __syncthreads();
    for (int base = 0; base < NN; base += 1024) {
        int i = base + t;
        int v = (i < NN) ? g_deg[i] : 0;
        int s = v;
        #pragma unroll
        for (int off = 1; off < 32; off <<= 1) {
            int x = __shfl_up_sync(0xffffffffu, s, off);
            if (lane >= off) s += x;
        }
        if (lane == 31) warpsums[wid] = s;
        __syncthreads();
        if (wid == 0) {
            int ws = warpsums[lane];
            int sc = ws;
            #pragma unroll
            for (int off = 1; off < 32; off <<= 1) {
                int x = __shfl_up_sync(0xffffffffu, sc, off);
                if (lane >= off) sc += x;
            }
            warpsums[lane] = sc - ws;   // exclusive warp prefix
            if (lane == 31) s_tot = sc; // chunk total
        }
        __syncthreads();
        int incl = warpsums[wid] + s;
        if (i < NN) g_off[i] = s_carry + incl - v;
        __syncthreads();
        if (t == 0) s_carry += s_tot;
        __syncthreads();
    }
    if (threadIdx.x == 0) g_off[NN] = s_carry;
}

__global__ void scatter_kernel(const int* __restrict__ src, const int* __restrict__ dst) {
    int e = blockIdx.x * blockDim.x + threadIdx.x;
    if (e < EE) {
        int d = dst[e];
        int pos = atomicAdd(&g_cur[d], 1);
        g_csr[g_off[d] + pos] = src[e];
    }
}

// Build dense x_sparse rows. One warp per row; last-wins duplicate semantics
// (scan k ascending, later k overwrites) computed entirely in registers.
__global__ void xs_kernel(const float* __restrict__ tv, const int* __restrict__ ti) {
    __shared__ int   sidx[8][32];
    __shared__ float sval[8][32];
    int w = threadIdx.x >> 5, lane = threadIdx.x & 31;
    int row = blockIdx.x * 8 + w;
    if (row >= NN) return;
    sidx[w][lane] = ti[row * KK + lane];
    sval[w][lane] = tv[row * KK + lane];
    __syncwarp();
    float r0 = 0.f, r1 = 0.f, r2 = 0.f, r3 = 0.f;
    #pragma unroll
    for (int j = 0; j < 32; j++) {
        int c = sidx[w][j];
        float v = sval[w][j];
        if ((c >> 2) == lane) {
            int sub = c & 3;
            if      (sub == 0) r0 = v;
            else if (sub == 1) r1 = v;
            else if (sub == 2) r2 = v;
            else               r3 = v;
        }
    }
    *(float4*)&g_xs[(size_t)row * FIN + lane * 4] = make_float4(r0, r1, r2, r3);
}

// One warp per dst node: sum dense x_sparse rows of its neighbors (register
// accumulators, float4 per lane), scale by 1/max(deg,1). No atomics.
__global__ void agg_kernel() {
    int gw = (blockIdx.x * blockDim.x + threadIdx.x) >> 5;
    int lane = threadIdx.x & 31;
    if (gw >= NN) return;
    int start = g_off[gw], end = g_off[gw + 1];
    float4 acc = make_float4(0.f, 0.f, 0.f, 0.f);
    for (int chunk = start; chunk < end; chunk += 32) {
        int i = chunk + lane;
        int s = (i < end) ? g_csr[i] : 0;
        int m = min(32, end - chunk);
        for (int j = 0; j < m; j++) {
            int ss = __shfl_sync(0xffffffffu, s, j);
            const float4 x = *(const float4*)&g_xs[(size_t)ss * FIN + lane * 4];
            acc.x += x.x; acc.y += x.y; acc.z += x.z; acc.w += x.w;
        }
    }
    int deg = end - start;
    float wgt = 1.0f / (float)max(deg, 1);
    acc.x *= wgt; acc.y *= wgt; acc.z *= wgt; acc.w *= wgt;
    *(float4*)&g_agg[(size_t)gw * FIN + lane * 4] = acc;
}

// out = [feat | agg] @ [[W_self],[W_neigh]] + b  (K = 256 fused)
// 128x128 block tile, 256 threads, 8x8 per thread, BK=8, gmem prefetch.
__global__ __launch_bounds__(256, 2)
void gemm_kernel(const float* __restrict__ feat,
                 const float* __restrict__ Wself,
                 const float* __restrict__ bself,
                 const float* __restrict__ Wneigh,
                 float* __restrict__ out) {
    __shared__ float sA[8][128];
    __shared__ float sB[8][128];
    const int t = threadIdx.x;
    const int tx = t & 15, ty = t >> 4;
    const int rowBase = blockIdx.x * 128;
    const int aRow = t >> 1, aCol = (t & 1) * 4;
    const int bRow = t >> 5, bCol = (t & 31) * 4;
    const int gr = rowBase + aRow;

    float acc[8][8];
    #pragma unroll
    for (int r = 0; r < 8; r++)
        #pragma unroll
        for (int c = 0; c < 8; c++) acc[r][c] = 0.f;

    // prefetch k0 = 0
    float4 av = (gr < NN) ? *(const float4*)(feat + (size_t)gr * FIN + aCol)
                          : make_float4(0.f, 0.f, 0.f, 0.f);
    float4 bv = *(const float4*)(Wself + bRow * 128 + bCol);

    for (int k0 = 0; k0 < 256; k0 += 8) {
        __syncthreads();
        sA[aCol + 0][aRow] = av.x;
        sA[aCol + 1][aRow] = av.y;
        sA[aCol + 2][aRow] = av.z;
        sA[aCol + 3][aRow] = av.w;
        *(float4*)&sB[bRow][bCol] = bv;
        __syncthreads();

        int k1 = k0 + 8;
        if (k1 < 256) {
            const float* Ab2; const float* Wb2; int ko;
            if (k1 < 128) { Ab2 = feat;  Wb2 = Wself;  ko = k1; }
            else          { Ab2 = g_agg; Wb2 = Wneigh; ko = k1 - 128; }
            av = (gr < NN) ? *(const float4*)(Ab2 + (size_t)gr * FIN + ko + aCol)
                           : make_float4(0.f, 0.f, 0.f, 0.f);
            bv = *(const float4*)(Wb2 + (ko + bRow) * 128 + bCol);
        }

        #pragma unroll
        for (int k = 0; k < 8; k++) {
            float4 a0 = *(float4*)&sA[k][ty * 8];
            float4 a1 = *(float4*)&sA[k][ty * 8 + 4];
            float4 b0 = *(float4*)&sB[k][tx * 8];
            float4 b1 = *(float4*)&sB[k][tx * 8 + 4];
            float a[8] = {a0.x, a0.y, a0.z, a0.w, a1.x, a1.y, a1.z, a1.w};
            float b[8] = {b0.x, b0.y, b0.z, b0.w, b1.x, b1.y, b1.z, b1.w};
            #pragma unroll
            for (int r = 0; r < 8; r++)
                #pragma unroll
                for (int c = 0; c < 8; c++)
                    acc[r][c] += a[r] * b[c];
        }
    }

    float bias[8];
    #pragma unroll
    for (int c = 0; c < 8; c++) bias[c] = bself[tx * 8 + c];

    #pragma unroll
    for (int r = 0; r < 8; r++) {
        int grr = rowBase + ty * 8 + r;
        if (grr < NN) {
            float4 o0 = make_float4(acc[r][0] + bias[0], acc[r][1] + bias[1],
                                    acc[r][2] + bias[2], acc[r][3] + bias[3]);
            float4 o1 = make_float4(acc[r][4] + bias[4], acc[r][5] + bias[5],
                                    acc[r][6] + bias[6], acc[r][7] + bias[7]);
            *(float4*)&out[(size_t)grr * FIN + tx * 8]     = o0;
            *(float4*)&out[(size_t)grr * FIN + tx * 8 + 4] = o1;
        }
    }
}

// ---------------- launch ----------------
extern "C" void kernel_launch(void* const* d_in, const int* in_sizes, int n_in,
                              void* d_out, int out_size) {
    const float *feat = nullptr, *topkv = nullptr, *Wself = nullptr,
                *bself = nullptr, *Wneigh = nullptr;
    const int *topki = nullptr, *src = nullptr, *dst = nullptr;

    for (int i = 0; i < n_in; i++) {
        int s = in_sizes[i];
        const void* p = d_in[i];
        if (s == NN * FIN)       feat = (const float*)p;
        else if (s == NN * KK) { if (!topkv) topkv = (const float*)p; else topki = (const int*)p; }
        else if (s == EE)      { if (!src)   src   = (const int*)p;   else dst   = (const int*)p; }
        else if (s == 128*128) { if (!Wself) Wself = (const float*)p; else Wneigh = (const float*)p; }
        else if (s == 128)       bself = (const float*)p;
    }
    float* out = (float*)d_out;

    init_kernel<<<(NN + 511) / 512, 512>>>();
    deg_kernel<<<(EE + 255) / 256, 256>>>(dst);
    scan_kernel<<<1, 1024>>>();
    scatter_kernel<<<(EE + 255) / 256, 256>>>(src, dst);
    xs_kernel<<<(NN + 7) / 8, 256>>>(topkv, topki);
    agg_kernel<<<(NN + 7) / 8, 256>>>();
    gemm_kernel<<<(NN + 127) / 128, 256>>>(feat, Wself, bself, Wneigh, out);
}

// round 2
// speedup vs baseline: 1.2446x; 1.2446x over previous
#include <cuda_runtime.h>
#include <cstdint>

#define NN  50000
#define EE  800000
#define FIN 128
#define KK  32
#define NB_SCAN ((NN + 1023) / 1024)

typedef unsigned long long u64;

// ---------------- device scratch (no allocations allowed) ----------------
__device__ float g_xs[(size_t)NN * FIN];    // dense MaxK-sparsified features
__device__ float g_agg[(size_t)NN * FIN];   // normalized neighbor aggregate
__device__ int   g_deg[NN];
__device__ int   g_off[NN + 1];
__device__ int   g_cur[NN];
__device__ int   g_bsum[64];
__device__ int   g_csr[EE];                 // src ids grouped by dst

// ---------------- f32x2 helpers ----------------
__device__ __forceinline__ u64 pack2(float lo, float hi) {
    u64 r; asm("mov.b64 %0, {%1, %2};" : "=l"(r) : "f"(lo), "f"(hi)); return r;
}
__device__ __forceinline__ void ffma2(u64& d, u64 a, u64 b) {
    asm("fma.rn.f32x2 %0, %1, %2, %0;" : "+l"(d) : "l"(a), "l"(b));
}
__device__ __forceinline__ void fadd2(u64& d, u64 a) {
    asm("add.rn.f32x2 %0, %0, %1;" : "+l"(d) : "l"(a));
}

// ---------------- kernels ----------------

__global__ void init_kernel() {
    int i = blockIdx.x * blockDim.x + threadIdx.x;
    if (i < NN) { g_deg[i] = 0; g_cur[i] = 0; }
}

__global__ void deg_kernel(const int* __restrict__ dst) {
    int e = blockIdx.x * blockDim.x + threadIdx.x;
    if (e < EE) atomicAdd(&g_deg[dst[e]], 1);
}

// phase 1: each 1024-thread block scans its 1024-element chunk (exclusive,
// local) into g_off, chunk total into g_bsum[block]
__global__ void scan1_kernel() {
    __shared__ int wsum[32];
    int t = threadIdx.x, lane = t & 31, wid = t >> 5;
    int i = blockIdx.x * 1024 + t;
    int v = (i < NN) ? g_deg[i] : 0;
    int s = v;
    #pragma unroll
    for (int off = 1; off < 32; off <<= 1) {
        int x = __shfl_up_sync(0xffffffffu, s, off);
        if (lane >= off) s += x;
    }
    if (lane == 31) wsum[wid] = s;
    __syncthreads();
    if (wid == 0) {
        int ws = wsum[lane];
        int sc = ws;
        #pragma unroll
        for (int off = 1; off < 32; off <<= 1) {
            int x = __shfl_up_sync(0xffffffffu, sc, off);
            if (lane >= off) sc += x;
        }
        wsum[lane] = sc - ws;          // exclusive warp prefix
        if (lane == 31) g_bsum[blockIdx.x] = sc;
    }
    __syncthreads();
    if (i < NN) g_off[i] = wsum[wid] + s - v;
}

// phase 2: one warp scans the block sums (exclusive), writes grand total
__global__ void scan2_kernel() {
    int lane = threadIdx.x;
    int carry = 0;
    for (int base = 0; base < NB_SCAN; base += 32) {
        int i = base + lane;
        int v = (i < NB_SCAN) ? g_bsum[i] : 0;
        int s = v;
        #pragma unroll
        for (int off = 1; off < 32; off <<= 1) {
            int x = __shfl_up_sync(0xffffffffu, s, off);
            if (lane >= off) s += x;
        }
        if (i < NB_SCAN) g_bsum[i] = carry + s - v;
        carry += __shfl_sync(0xffffffffu, s, 31);
    }
    if (lane == 0) g_off[NN] = carry;
}

// phase 3: add block offsets
__global__ void scan3_kernel() {
    int i = blockIdx.x * blockDim.x + threadIdx.x;
    if (i < NN) g_off[i] += g_bsum[i >> 10];
}

__global__ void scatter_kernel(const int* __restrict__ src, const int* __restrict__ dst) {
    int e = blockIdx.x * blockDim.x + threadIdx.x;
    if (e < EE) {
        int d = dst[e];
        int pos = atomicAdd(&g_cur[d], 1);
        g_csr[g_off[d] + pos] = src[e];
    }
}

// Build dense x_sparse rows. One warp per row; last-wins duplicate semantics.
__global__ void xs_kernel(const float* __restrict__ tv, const int* __restrict__ ti) {
    __shared__ int   sidx[8][32];
    __shared__ float sval[8][32];
    int w = threadIdx.x >> 5, lane = threadIdx.x & 31;
    int row = blockIdx.x * 8 + w;
    if (row >= NN) return;
    sidx[w][lane] = ti[row * KK + lane];
    sval[w][lane] = tv[row * KK + lane];
    __syncwarp();
    float r0 = 0.f, r1 = 0.f, r2 = 0.f, r3 = 0.f;
    #pragma unroll
    for (int j = 0; j < 32; j++) {
        int c = sidx[w][j];
        float v = sval[w][j];
        if ((c >> 2) == lane) {
            int sub = c & 3;
            if      (sub == 0) r0 = v;
            else if (sub == 1) r1 = v;
            else if (sub == 2) r2 = v;
            else               r3 = v;
        }
    }
    *(float4*)&g_xs[(size_t)row * FIN + lane * 4] = make_float4(r0, r1, r2, r3);
}

// One warp per dst node: sum dense x_sparse rows of its neighbors.
__global__ void agg_kernel() {
    int gw = (blockIdx.x * blockDim.x + threadIdx.x) >> 5;
    int lane = threadIdx.x & 31;
    if (gw >= NN) return;
    int start = g_off[gw], end = g_off[gw + 1];
    float4 acc = make_float4(0.f, 0.f, 0.f, 0.f);
    for (int chunk = start; chunk < end; chunk += 32) {
        int i = chunk + lane;
        int s = (i < end) ? g_csr[i] : 0;
        int m = min(32, end - chunk);
        for (int j = 0; j < m; j++) {
            int ss = __shfl_sync(0xffffffffu, s, j);
            const float4 x = *(const float4*)&g_xs[(size_t)ss * FIN + lane * 4];
            acc.x += x.x; acc.y += x.y; acc.z += x.z; acc.w += x.w;
        }
    }
    int deg = end - start;
    float wgt = 1.0f / (float)max(deg, 1);
    acc.x *= wgt; acc.y *= wgt; acc.z *= wgt; acc.w *= wgt;
    *(float4*)&g_agg[(size_t)gw * FIN + lane * 4] = acc;
}

// out = [feat | agg] @ [[W_self],[W_neigh]] + b  (K = 256 fused)
// 128x128 block tile, 256 threads, 8x8 per thread, BK=8, packed f32x2 FMA.
__global__ __launch_bounds__(256, 2)
void gemm_kernel(const float* __restrict__ feat,
                 const float* __restrict__ Wself,
                 const float* __restrict__ bself,
                 const float* __restrict__ Wneigh,
                 float* __restrict__ out) {
    __shared__ float sA[8][128];
    __shared__ float sB[8][128];
    const int t = threadIdx.x;
    const int tx = t & 15, ty = t >> 4;
    const int rowBase = blockIdx.x * 128;
    const int aRow = t >> 1, aCol = (t & 1) * 4;
    const int bRow = t >> 5, bCol = (t & 31) * 4;
    const int gr = rowBase + aRow;

    u64 acc2[8][4];
    #pragma unroll
    for (int r = 0; r < 8; r++)
        #pragma unroll
        for (int c = 0; c < 4; c++) acc2[r][c] = 0ull;

    // prefetch k0 = 0
    float4 av = (gr < NN) ? *(const float4*)(feat + (size_t)gr * FIN + aCol)
                          : make_float4(0.f, 0.f, 0.f, 0.f);
    float4 bv = *(const float4*)(Wself + bRow * 128 + bCol);

    for (int k0 = 0; k0 < 256; k0 += 8) {
        __syncthreads();
        sA[aCol + 0][aRow] = av.x;
        sA[aCol + 1][aRow] = av.y;
        sA[aCol + 2][aRow] = av.z;
        sA[aCol + 3][aRow] = av.w;
        *(float4*)&sB[bRow][bCol] = bv;
        __syncthreads();

        int k1 = k0 + 8;
        if (k1 < 256) {
            const float* Ab2; const float* Wb2; int ko;
            if (k1 < 128) { Ab2 = feat;  Wb2 = Wself;  ko = k1; }
            else          { Ab2 = g_agg; Wb2 = Wneigh; ko = k1 - 128; }
            av = (gr < NN) ? *(const float4*)(Ab2 + (size_t)gr * FIN + ko + aCol)
                           : make_float4(0.f, 0.f, 0.f, 0.f);
            bv = *(const float4*)(Wb2 + (ko + bRow) * 128 + bCol);
        }

        #pragma unroll
        for (int k = 0; k < 8; k++) {
            float4 a0 = *(float4*)&sA[k][ty * 8];
            float4 a1 = *(float4*)&sA[k][ty * 8 + 4];
            float4 b0 = *(float4*)&sB[k][tx * 8];
            float4 b1 = *(float4*)&sB[k][tx * 8 + 4];
            u64 bp[4] = { pack2(b0.x, b0.y), pack2(b0.z, b0.w),
                          pack2(b1.x, b1.y), pack2(b1.z, b1.w) };
            float a[8] = {a0.x, a0.y, a0.z, a0.w, a1.x, a1.y, a1.z, a1.w};
            #pragma unroll
            for (int r = 0; r < 8; r++) {
                u64 ap = pack2(a[r], a[r]);
                #pragma unroll
                for (int c = 0; c < 4; c++)
                    ffma2(acc2[r][c], ap, bp[c]);
            }
        }
    }

    // bias, packed
    u64 bias2[4];
    #pragma unroll
    for (int c = 0; c < 4; c++)
        bias2[c] = pack2(bself[tx * 8 + c * 2], bself[tx * 8 + c * 2 + 1]);

    #pragma unroll
    for (int r = 0; r < 8; r++) {
        int grr = rowBase + ty * 8 + r;
        if (grr < NN) {
            #pragma unroll
            for (int c = 0; c < 4; c++) fadd2(acc2[r][c], bias2[c]);
            ulonglong2 o0, o1;
            o0.x = acc2[r][0]; o0.y = acc2[r][1];
            o1.x = acc2[r][2]; o1.y = acc2[r][3];
            *(ulonglong2*)&out[(size_t)grr * FIN + tx * 8]     = o0;
            *(ulonglong2*)&out[(size_t)grr * FIN + tx * 8 + 4] = o1;
        }
    }
}

// ---------------- launch ----------------
extern "C" void kernel_launch(void* const* d_in, const int* in_sizes, int n_in,
                              void* d_out, int out_size) {
    const float *feat = nullptr, *topkv = nullptr, *Wself = nullptr,
                *bself = nullptr, *Wneigh = nullptr;
    const int *topki = nullptr, *src = nullptr, *dst = nullptr;

    for (int i = 0; i < n_in; i++) {
        int s = in_sizes[i];
        const void* p = d_in[i];
        if (s == NN * FIN)       feat = (const float*)p;
        else if (s == NN * KK) { if (!topkv) topkv = (const float*)p; else topki = (const int*)p; }
        else if (s == EE)      { if (!src)   src   = (const int*)p;   else dst   = (const int*)p; }
        else if (s == 128*128) { if (!Wself) Wself = (const float*)p; else Wneigh = (const float*)p; }
        else if (s == 128)       bself = (const float*)p;
    }
    float* out = (float*)d_out;

    init_kernel<<<(NN + 511) / 512, 512>>>();
    deg_kernel<<<(EE + 255) / 256, 256>>>(dst);
    scan1_kernel<<<NB_SCAN, 1024>>>();
    scan2_kernel<<<1, 32>>>();
    scan3_kernel<<<(NN + 511) / 512, 512>>>();
    scatter_kernel<<<(EE + 255) / 256, 256>>>(src, dst);
    xs_kernel<<<(NN + 7) / 8, 256>>>(topkv, topki);
    agg_kernel<<<(NN + 7) / 8, 256>>>();
    gemm_kernel<<<(NN + 127) / 128, 256>>>(feat, Wself, bself, Wneigh, out);
}

// round 4
// speedup vs baseline: 1.4574x; 1.1710x over previous
#include <cuda_runtime.h>
#include <cuda_bf16.h>
#include <cstdint>

#define NN  50000
#define EE  800000
#define FIN 128
#define KK  32
#define NB_SCAN ((NN + 1023) / 1024)
#define AS  136   // smem tile stride in bf16 elems (128 + 8 pad)

typedef unsigned long long u64;

// ---------------- device scratch (no allocations allowed) ----------------
__device__ float g_xs[(size_t)NN * FIN];    // dense MaxK-sparsified features
__device__ float g_agg[(size_t)NN * FIN];   // normalized neighbor aggregate
__device__ int   g_deg[NN];
__device__ int   g_off[NN + 1];
__device__ int   g_cur[NN];
__device__ int   g_bsum[64];
__device__ int   g_csr[EE];                 // src ids grouped by dst
__device__ __nv_bfloat16 g_whi[2][128 * 128];  // W^T split-hi, [phase][n][k]
__device__ __nv_bfloat16 g_wlo[2][128 * 128];  // W^T split-lo

// ---------------- PTX helpers (baseline sm_80-class only) ----------------
__device__ __forceinline__ uint32_t smem_u32(const void* p) {
    uint32_t a;
    asm("{ .reg .u64 t; cvta.to.shared.u64 t, %1; cvt.u32.u64 %0, t; }" : "=r"(a) : "l"(p));
    return a;
}
__device__ __forceinline__ void ldm_x4(uint32_t* r, uint32_t addr) {
    asm volatile("ldmatrix.sync.aligned.m8n8.x4.shared.b16 {%0,%1,%2,%3}, [%4];"
                 : "=r"(r[0]), "=r"(r[1]), "=r"(r[2]), "=r"(r[3]) : "r"(addr));
}
__device__ __forceinline__ void mma_bf16(float* c, const uint32_t* a, uint32_t b0, uint32_t b1) {
    asm volatile(
        "mma.sync.aligned.m16n8k16.row.col.f32.bf16.bf16.f32 "
        "{%0,%1,%2,%3}, {%4,%5,%6,%7}, {%8,%9}, {%0,%1,%2,%3};"
        : "+f"(c[0]), "+f"(c[1]), "+f"(c[2]), "+f"(c[3])
        : "r"(a[0]), "r"(a[1]), "r"(a[2]), "r"(a[3]), "r"(b0), "r"(b1));
}
// ldmatrix.x4 address for a 16x16 tile at (row, col) in a [128][AS] bf16 tile
__device__ __forceinline__ uint32_t ldm_addr(uint32_t base, int row, int col, int lane) {
    int r = row + (lane & 15);
    int c = col + ((lane >> 4) << 3);
    return base + (uint32_t)((r * AS + c) * 2);
}

// ---------------- small kernels ----------------

__global__ void init_kernel() {
    int i = blockIdx.x * blockDim.x + threadIdx.x;
    if (i < NN) { g_deg[i] = 0; g_cur[i] = 0; }
}

__global__ void deg_kernel(const int* __restrict__ dst) {
    int e = blockIdx.x * blockDim.x + threadIdx.x;
    if (e < EE) atomicAdd(&g_deg[dst[e]], 1);
}

// phase 1: per-1024 chunk local exclusive scan -> g_off, chunk totals -> g_bsum
__global__ void scan1_kernel() {
    __shared__ int wsum[32];
    int t = threadIdx.x, lane = t & 31, wid = t >> 5;
    int i = blockIdx.x * 1024 + t;
    int v = (i < NN) ? g_deg[i] : 0;
    int s = v;
    #pragma unroll
    for (int off = 1; off < 32; off <<= 1) {
        int x = __shfl_up_sync(0xffffffffu, s, off);
        if (lane >= off) s += x;
    }
    if (lane == 31) wsum[wid] = s;
    __syncthreads();
    if (wid == 0) {
        int ws = wsum[lane];
        int sc = ws;
        #pragma unroll
        for (int off = 1; off < 32; off <<= 1) {
            int x = __shfl_up_sync(0xffffffffu, sc, off);
            if (lane >= off) sc += x;
        }
        wsum[lane] = sc - ws;
        if (lane == 31) g_bsum[blockIdx.x] = sc;
    }
    __syncthreads();
    if (i < NN) g_off[i] = wsum[wid] + s - v;
}

// phase 2+3 fused: each block warp-scans all chunk totals, adds its prefix
__global__ void scan3_kernel() {
    __shared__ int s_add;
    int t = threadIdx.x, b = blockIdx.x;
    if (t < 32) {
        int tot = 0;
        for (int base = 0; base < NB_SCAN; base += 32) {
            int i = base + t;
            int v = (i < NB_SCAN) ? g_bsum[i] : 0;
            int s = v;
            #pragma unroll
            for (int off = 1; off < 32; off <<= 1) {
                int x = __shfl_up_sync(0xffffffffu, s, off);
                if (t >= off) s += x;
            }
            if (i == b) s_add = tot + s - v;     // exclusive prefix for chunk b
            tot += __shfl_sync(0xffffffffu, s, 31);
        }
        if (t == 0 && b == 0) g_off[NN] = tot;
    }
    __syncthreads();
    int i = b * 1024 + t;
    if (i < NN) g_off[i] += s_add;
}

__global__ void scatter_kernel(const int* __restrict__ src, const int* __restrict__ dst) {
    int e = blockIdx.x * blockDim.x + threadIdx.x;
    if (e < EE) {
        int d = dst[e];
        int pos = atomicAdd(&g_cur[d], 1);
        g_csr[g_off[d] + pos] = src[e];
    }
}

// Dense x_sparse rows; last-wins duplicate semantics.
__global__ void xs_kernel(const float* __restrict__ tv, const int* __restrict__ ti) {
    __shared__ int   sidx[8][32];
    __shared__ float sval[8][32];
    int w = threadIdx.x >> 5, lane = threadIdx.x & 31;
    int row = blockIdx.x * 8 + w;
    if (row >= NN) return;
    sidx[w][lane] = ti[row * KK + lane];
    sval[w][lane] = tv[row * KK + lane];
    __syncwarp();
    float r0 = 0.f, r1 = 0.f, r2 = 0.f, r3 = 0.f;
    #pragma unroll
    for (int j = 0; j < 32; j++) {
        int c = sidx[w][j];
        float v = sval[w][j];
        if ((c >> 2) == lane) {
            int sub = c & 3;
            if      (sub == 0) r0 = v;
            else if (sub == 1) r1 = v;
            else if (sub == 2) r2 = v;
            else               r3 = v;
        }
    }
    *(float4*)&g_xs[(size_t)row * FIN + lane * 4] = make_float4(r0, r1, r2, r3);
}

// One warp per dst node: sum dense x_sparse rows of its neighbors.
__global__ void agg_kernel() {
    int gw = (blockIdx.x * blockDim.x + threadIdx.x) >> 5;
    int lane = threadIdx.x & 31;
    if (gw >= NN) return;
    int start = g_off[gw], end = g_off[gw + 1];
    float4 acc = make_float4(0.f, 0.f, 0.f, 0.f);
    for (int chunk = start; chunk < end; chunk += 32) {
        int i = chunk + lane;
        int s = (i < end) ? g_csr[i] : 0;
        int m = min(32, end - chunk);
        for (int j = 0; j < m; j++) {
            int ss = __shfl_sync(0xffffffffu, s, j);
            const float4 x = *(const float4*)&g_xs[(size_t)ss * FIN + lane * 4];
            acc.x += x.x; acc.y += x.y; acc.z += x.z; acc.w += x.w;
        }
    }
    int deg = end - start;
    float wgt = 1.0f / (float)max(deg, 1);
    acc.x *= wgt; acc.y *= wgt; acc.z *= wgt; acc.w *= wgt;
    *(float4*)&g_agg[(size_t)gw * FIN + lane * 4] = acc;
}

// W^T + bf16 hi/lo split:  g_w*[ph][n][k] = split(W[k][n])
__global__ void wprep_kernel(const float* __restrict__ Ws, const float* __restrict__ Wn) {
    int i = blockIdx.x * blockDim.x + threadIdx.x;   // 0..16383, = k*128+n
    int ph = blockIdx.y;
    const float* W = ph ? Wn : Ws;
    float v = W[i];
    int k = i >> 7, n = i & 127;
    __nv_bfloat16 h = __float2bfloat16(v);
    float lo = v - __bfloat162float(h);
    g_whi[ph][n * 128 + k] = h;
    g_wlo[ph][n * 128 + k] = __float2bfloat16(lo);
}

// ---------------- HMMA split-bf16 GEMM ----------------
// out = [feat | agg] @ [[W_self],[W_neigh]] + b
// 128x128 CTA tile, 8 warps x (32 rows x 64 cols), K in two 128-phases.
// Each fp32 operand split hi+lo bf16; 3 MMAs (hi*hi, hi*lo, lo*hi).

#define SM_AHI 0
#define SM_ALO (128 * AS * 2)
#define SM_BHI (2 * 128 * AS * 2)
#define SM_BLO (3 * 128 * AS * 2)
#define SM_TOTAL (4 * 128 * AS * 2)

__global__ void __launch_bounds__(256, 1) gemm_kernel(
    const float* __restrict__ feat,
    const float* __restrict__ bself,
    float* __restrict__ out)
{
    extern __shared__ char smem[];
    uint32_t sb = smem_u32(smem);
    const int t = threadIdx.x, w = t >> 5, lane = t & 31;
    const int rowBase = blockIdx.x * 128;
    const int wm = (w & 3) * 32;        // warp row offset in tile
    const int wn = (w >> 2) * 64;       // warp col offset in tile

    float acc[2][8][4];
    #pragma unroll
    for (int mf = 0; mf < 2; mf++)
        #pragma unroll
        for (int nf = 0; nf < 8; nf++)
            #pragma unroll
            for (int e = 0; e < 4; e++) acc[mf][nf][e] = 0.f;

    const int fr = t >> 1;      // fill row 0..127
    const int half = t & 1;     // fill col half

    #pragma unroll
    for (int ph = 0; ph < 2; ph++) {
        const float* Asrc = ph ? g_agg : feat;
        const int gr = rowBase + fr;
        const bool valid = gr < NN;

        if (ph) __syncthreads();   // protect smem reuse from previous phase

        // ---- A fill: fp32 -> bf16 hi/lo into padded [128][AS] tiles ----
        #pragma unroll 4
        for (int j = 0; j < 16; j++) {
            int c = half * 64 + j * 4;
            float4 v = valid ? *(const float4*)(Asrc + (size_t)gr * FIN + c)
                             : make_float4(0.f, 0.f, 0.f, 0.f);
            __nv_bfloat16 hx = __float2bfloat16(v.x), hy = __float2bfloat16(v.y);
            __nv_bfloat16 hz = __float2bfloat16(v.z), hw = __float2bfloat16(v.w);
            __nv_bfloat16 lx = __float2bfloat16(v.x - __bfloat162float(hx));
            __nv_bfloat16 ly = __float2bfloat16(v.y - __bfloat162float(hy));
            __nv_bfloat16 lz = __float2bfloat16(v.z - __bfloat162float(hz));
            __nv_bfloat16 lw = __float2bfloat16(v.w - __bfloat162float(hw));
            uint32_t o = (uint32_t)((fr * AS + c) * 2);
            *(__nv_bfloat162*)(smem + SM_AHI + o)     = __halves2bfloat162(hx, hy);
            *(__nv_bfloat162*)(smem + SM_AHI + o + 4) = __halves2bfloat162(hz, hw);
            *(__nv_bfloat162*)(smem + SM_ALO + o)     = __halves2bfloat162(lx, ly);
            *(__nv_bfloat162*)(smem + SM_ALO + o + 4) = __halves2bfloat162(lz, lw);
        }
        // ---- B fill: copy pre-split W^T [n][k] rows ----
        {
            uint32_t o = (uint32_t)((fr * AS + half * 64) * 2);
            const uint4* srcH = (const uint4*)(g_whi[ph] + fr * 128 + half * 64);
            const uint4* srcL = (const uint4*)(g_wlo[ph] + fr * 128 + half * 64);
            #pragma unroll
            for (int j = 0; j < 8; j++) {
                *(uint4*)(smem + SM_BHI + o + j * 16) = srcH[j];
                *(uint4*)(smem + SM_BLO + o + j * 16) = srcL[j];
            }
        }
        __syncthreads();

        // ---- MMA mainloop: 8 k-steps of 16 ----
        #pragma unroll
        for (int ks = 0; ks < 8; ks++) {
            const int kb = ks * 16;
            uint32_t ahi[2][4], alo[2][4];
            #pragma unroll
            for (int mf = 0; mf < 2; mf++) {
                ldm_x4(ahi[mf], ldm_addr(sb + SM_AHI, wm + mf * 16, kb, lane));
                ldm_x4(alo[mf], ldm_addr(sb + SM_ALO, wm + mf * 16, kb, lane));
            }
            uint32_t bhi[4][4], blo[4][4];
            #pragma unroll
            for (int nb = 0; nb < 4; nb++) {
                ldm_x4(bhi[nb], ldm_addr(sb + SM_BHI, wn + nb * 16, kb, lane));
                ldm_x4(blo[nb], ldm_addr(sb + SM_BLO, wn + nb * 16, kb, lane));
            }
            #pragma unroll
            for (int mf = 0; mf < 2; mf++)
                #pragma unroll
                for (int nf = 0; nf < 8; nf++) {
                    int nb = nf >> 1, sel = nf & 1;
                    uint32_t bh0 = bhi[nb][sel], bh1 = bhi[nb][sel + 2];
                    uint32_t bl0 = blo[nb][sel], bl1 = blo[nb][sel + 2];
                    mma_bf16(acc[mf][nf], ahi[mf], bh0, bh1);
                    mma_bf16(acc[mf][nf], ahi[mf], bl0, bl1);
                    mma_bf16(acc[mf][nf], alo[mf], bh0, bh1);
                }
        }
    }

    // ---- epilogue: +bias, store ----
    const int cg = (lane & 3) * 2;     // col pair within n-frag
    const int rr = lane >> 2;          // row within m-frag half
    #pragma unroll
    for (int mf = 0; mf < 2; mf++) {
        int r0 = rowBase + wm + mf * 16 + rr;
        int r1 = r0 + 8;
        #pragma unroll
        for (int nf = 0; nf < 8; nf++) {
            int col = wn + nf * 8 + cg;
            float b0 = __ldg(bself + col), b1 = __ldg(bself + col + 1);
            if (r0 < NN) {
                float2 o = make_float2(acc[mf][nf][0] + b0, acc[mf][nf][1] + b1);
                *(float2*)(out + (size_t)r0 * FIN + col) = o;
            }
            if (r1 < NN) {
                float2 o = make_float2(acc[mf][nf][2] + b0, acc[mf][nf][3] + b1);
                *(float2*)(out + (size_t)r1 * FIN + col) = o;
            }
        }
    }
}

// ---------------- launch ----------------
extern "C" void kernel_launch(void* const* d_in, const int* in_sizes, int n_in,
                              void* d_out, int out_size) {
    const float *feat = nullptr, *topkv = nullptr, *Wself = nullptr,
                *bself = nullptr, *Wneigh = nullptr;
    const int *topki = nullptr, *src = nullptr, *dst = nullptr;

    for (int i = 0; i < n_in; i++) {
        int s = in_sizes[i];
        const void* p = d_in[i];
        if (s == NN * FIN)       feat = (const float*)p;
        else if (s == NN * KK) { if (!topkv) topkv = (const float*)p; else topki = (const int*)p; }
        else if (s == EE)      { if (!src)   src   = (const int*)p;   else dst   = (const int*)p; }
        else if (s == 128*128) { if (!Wself) Wself = (const float*)p; else Wneigh = (const float*)p; }
        else if (s == 128)       bself = (const float*)p;
    }
    float* out = (float*)d_out;

    static int smem_set = 0;
    if (!smem_set) {
        cudaFuncSetAttribute(gemm_kernel, cudaFuncAttributeMaxDynamicSharedMemorySize, SM_TOTAL);
        smem_set = 1;
    }

    init_kernel<<<(NN + 511) / 512, 512>>>();
    deg_kernel<<<(EE + 255) / 256, 256>>>(dst);
    scan1_kernel<<<NB_SCAN, 1024>>>();
    scan3_kernel<<<NB_SCAN, 1024>>>();
    scatter_kernel<<<(EE + 255) / 256, 256>>>(src, dst);
    xs_kernel<<<(NN + 7) / 8, 256>>>(topkv, topki);
    wprep_kernel<<<dim3(64, 2), 256>>>(Wself, Wneigh);
    agg_kernel<<<(NN + 7) / 8, 256>>>();
    gemm_kernel<<<(NN + 127) / 128, 256, SM_TOTAL>>>(feat, bself, out);
}

// round 5
// speedup vs baseline: 1.5617x; 1.0716x over previous
#include <cuda_runtime.h>
#include <cuda_bf16.h>
#include <cstdint>

#define NN  50000
#define EE  800000
#define FIN 128
#define KK  32
#define NB_SCAN ((NN + 1023) / 1024)
#define AS  136   // smem tile stride in bf16 elems (128 + 8 pad)

typedef unsigned long long u64;

// ---------------- device scratch (no allocations allowed) ----------------
__device__ float g_xs[(size_t)NN * FIN];    // dense MaxK-sparsified features
__device__ float g_agg[(size_t)NN * FIN];   // normalized neighbor aggregate
__device__ int   g_deg[NN];
__device__ int   g_off[NN + 1];
__device__ int   g_cur[NN];
__device__ int   g_bsum[64];
__device__ int   g_csr[EE];                 // src ids grouped by dst
// Pre-built MMA B fragments: [ph][hilo][kstep(8)][wcol(2)][lane(32)][16]
__device__ uint32_t g_bf[2][2][8][2][32][16];

// ---------------- PTX helpers (baseline sm_80-class only) ----------------
__device__ __forceinline__ uint32_t smem_u32(const void* p) {
    uint32_t a;
    asm("{ .reg .u64 t; cvta.to.shared.u64 t, %1; cvt.u32.u64 %0, t; }" : "=r"(a) : "l"(p));
    return a;
}
__device__ __forceinline__ void ldm_x4(uint32_t* r, uint32_t addr) {
    asm volatile("ldmatrix.sync.aligned.m8n8.x4.shared.b16 {%0,%1,%2,%3}, [%4];"
                 : "=r"(r[0]), "=r"(r[1]), "=r"(r[2]), "=r"(r[3]) : "r"(addr));
}
__device__ __forceinline__ void mma_bf16(float* c, const uint32_t* a, uint32_t b0, uint32_t b1) {
    asm volatile(
        "mma.sync.aligned.m16n8k16.row.col.f32.bf16.bf16.f32 "
        "{%0,%1,%2,%3}, {%4,%5,%6,%7}, {%8,%9}, {%0,%1,%2,%3};"
        : "+f"(c[0]), "+f"(c[1]), "+f"(c[2]), "+f"(c[3])
        : "r"(a[0]), "r"(a[1]), "r"(a[2]), "r"(a[3]), "r"(b0), "r"(b1));
}
// ldmatrix.x4 address for a 16x16 tile at (row, col) in a [128][AS] bf16 tile
__device__ __forceinline__ uint32_t ldm_addr(uint32_t base, int row, int col, int lane) {
    int r = row + (lane & 15);
    int c = col + ((lane >> 4) << 3);
    return base + (uint32_t)((r * AS + c) * 2);
}

// ---------------- small kernels ----------------

__global__ void deg_kernel(const int* __restrict__ dst) {
    int i = (blockIdx.x * blockDim.x + threadIdx.x) * 4;
    if (i < EE) {
        int4 d = *(const int4*)(dst + i);
        atomicAdd(&g_deg[d.x], 1);
        atomicAdd(&g_deg[d.y], 1);
        atomicAdd(&g_deg[d.z], 1);
        atomicAdd(&g_deg[d.w], 1);
    }
}

// phase 1: per-1024 chunk local exclusive scan -> g_off, chunk totals -> g_bsum
__global__ void scan1_kernel() {
    __shared__ int wsum[32];
    int t = threadIdx.x, lane = t & 31, wid = t >> 5;
    int i = blockIdx.x * 1024 + t;
    int v = (i < NN) ? g_deg[i] : 0;
    int s = v;
    #pragma unroll
    for (int off = 1; off < 32; off <<= 1) {
        int x = __shfl_up_sync(0xffffffffu, s, off);
        if (lane >= off) s += x;
    }
    if (lane == 31) wsum[wid] = s;
    __syncthreads();
    if (wid == 0) {
        int ws = wsum[lane];
        int sc = ws;
        #pragma unroll
        for (int off = 1; off < 32; off <<= 1) {
            int x = __shfl_up_sync(0xffffffffu, sc, off);
            if (lane >= off) sc += x;
        }
        wsum[lane] = sc - ws;
        if (lane == 31) g_bsum[blockIdx.x] = sc;
    }
    __syncthreads();
    if (i < NN) g_off[i] = wsum[wid] + s - v;
}

// phase 2: one warp exclusively scans the chunk totals in place.
// g_off[NN] is set to the raw total of the LAST chunk so that
// g_off[NN] + g_bsum[NN>>10] == grand total.
__global__ void scan2_kernel() {
    int lane = threadIdx.x;
    int carry = 0;
    for (int base = 0; base < NB_SCAN; base += 32) {
        int i = base + lane;
        int v = (i < NB_SCAN) ? g_bsum[i] : 0;
        if (i == NB_SCAN - 1) g_off[NN] = v;
        int s = v;
        #pragma unroll
        for (int off = 1; off < 32; off <<= 1) {
            int x = __shfl_up_sync(0xffffffffu, s, off);
            if (lane >= off) s += x;
        }
        if (i < NB_SCAN) g_bsum[i] = carry + s - v;
        carry += __shfl_sync(0xffffffffu, s, 31);
    }
}

__global__ void scatter_kernel(const int* __restrict__ src, const int* __restrict__ dst) {
    int i = (blockIdx.x * blockDim.x + threadIdx.x) * 4;
    if (i < EE) {
        int4 d = *(const int4*)(dst + i);
        int4 s = *(const int4*)(src + i);
        int p;
        p = atomicAdd(&g_cur[d.x], 1); g_csr[g_off[d.x] + g_bsum[d.x >> 10] + p] = s.x;
        p = atomicAdd(&g_cur[d.y], 1); g_csr[g_off[d.y] + g_bsum[d.y >> 10] + p] = s.y;
        p = atomicAdd(&g_cur[d.z], 1); g_csr[g_off[d.z] + g_bsum[d.z >> 10] + p] = s.z;
        p = atomicAdd(&g_cur[d.w], 1); g_csr[g_off[d.w] + g_bsum[d.w >> 10] + p] = s.w;
    }
}

// Dense x_sparse rows; last-wins duplicate semantics.
__global__ void xs_kernel(const float* __restrict__ tv, const int* __restrict__ ti) {
    __shared__ int   sidx[8][32];
    __shared__ float sval[8][32];
    int w = threadIdx.x >> 5, lane = threadIdx.x & 31;
    int row = blockIdx.x * 8 + w;
    if (row >= NN) return;
    sidx[w][lane] = ti[row * KK + lane];
    sval[w][lane] = tv[row * KK + lane];
    __syncwarp();
    float r0 = 0.f, r1 = 0.f, r2 = 0.f, r3 = 0.f;
    #pragma unroll
    for (int j = 0; j < 32; j++) {
        int c = sidx[w][j];
        float v = sval[w][j];
        if ((c >> 2) == lane) {
            int sub = c & 3;
            if      (sub == 0) r0 = v;
            else if (sub == 1) r1 = v;
            else if (sub == 2) r2 = v;
            else               r3 = v;
        }
    }
    *(float4*)&g_xs[(size_t)row * FIN + lane * 4] = make_float4(r0, r1, r2, r3);
}

// One warp per dst node: sum dense x_sparse rows of its neighbors.
__global__ void agg_kernel() {
    int gw = (blockIdx.x * blockDim.x + threadIdx.x) >> 5;
    int lane = threadIdx.x & 31;
    if (gw >= NN) return;
    int start = g_off[gw] + g_bsum[gw >> 10];
    int end   = g_off[gw + 1] + g_bsum[(gw + 1) >> 10];
    float4 acc = make_float4(0.f, 0.f, 0.f, 0.f);
    for (int chunk = start; chunk < end; chunk += 32) {
        int i = chunk + lane;
        int s = (i < end) ? g_csr[i] : 0;
        int m = min(32, end - chunk);
        for (int j = 0; j < m; j++) {
            int ss = __shfl_sync(0xffffffffu, s, j);
            const float4 x = *(const float4*)&g_xs[(size_t)ss * FIN + lane * 4];
            acc.x += x.x; acc.y += x.y; acc.z += x.z; acc.w += x.w;
        }
    }
    int deg = end - start;
    float wgt = 1.0f / (float)max(deg, 1);
    acc.x *= wgt; acc.y *= wgt; acc.z *= wgt; acc.w *= wgt;
    *(float4*)&g_agg[(size_t)gw * FIN + lane * 4] = acc;
}

// Build per-thread MMA B fragments from W (row-major [k][n]), split hi/lo.
// Fragment element for (ks, wc, lane, nf, r):
//   k = ks*16 + (lane%4)*2 + r*8, n = wc*64 + nf*8 + lane/4, pair (k, k+1).
__global__ void wprep_kernel(const float* __restrict__ Ws, const float* __restrict__ Wn) {
    int idx = blockIdx.x * 256 + threadIdx.x;   // 0..32767
    int j    = idx & 15;
    int lane = (idx >> 4) & 31;
    int wc   = (idx >> 9) & 1;
    int ks   = (idx >> 10) & 7;
    int hl   = (idx >> 13) & 1;
    int ph   = (idx >> 14) & 1;
    int nf = j >> 1, r = j & 1;
    int k = ks * 16 + (lane & 3) * 2 + r * 8;
    int n = wc * 64 + nf * 8 + (lane >> 2);
    const float* W = ph ? Wn : Ws;
    float v0 = W[k * 128 + n];
    float v1 = W[(k + 1) * 128 + n];
    __nv_bfloat16 h0 = __float2bfloat16(v0);
    __nv_bfloat16 h1 = __float2bfloat16(v1);
    __nv_bfloat162 outp;
    if (hl == 0) outp = __halves2bfloat162(h0, h1);
    else outp = __halves2bfloat162(__float2bfloat16(v0 - __bfloat162float(h0)),
                                   __float2bfloat16(v1 - __bfloat162float(h1)));
    ((uint32_t*)g_bf)[idx] = *(uint32_t*)&outp;
}

// ---------------- HMMA split-bf16 GEMM ----------------
// out = [feat | agg] @ [[W_self],[W_neigh]] + b
// 128x128 CTA tile, 8 warps x (32 x 64), K in two 128-phases.
// A in smem (split hi/lo, ldmatrix); B direct from prebuilt gmem fragments.

#define SM_AHI 0
#define SM_ALO (128 * AS * 2)
#define SM_TOTAL (2 * 128 * AS * 2)   // 69,632 bytes

__global__ void __launch_bounds__(256, 2) gemm_kernel(
    const float* __restrict__ feat,
    const float* __restrict__ bself,
    float* __restrict__ out)
{
    extern __shared__ char smem[];
    uint32_t sb = smem_u32(smem);
    const int t = threadIdx.x, w = t >> 5, lane = t & 31;
    const int rowBase = blockIdx.x * 128;
    const int wm = (w & 3) * 32;        // warp row offset in tile
    const int wc = w >> 2;              // warp col half (0/1)

    float acc[2][8][4];
    #pragma unroll
    for (int mf = 0; mf < 2; mf++)
        #pragma unroll
        for (int nf = 0; nf < 8; nf++)
            #pragma unroll
            for (int e = 0; e < 4; e++) acc[mf][nf][e] = 0.f;

    const int fr = t >> 1;      // fill row 0..127
    const int half = t & 1;     // fill col half

    #pragma unroll
    for (int ph = 0; ph < 2; ph++) {
        const float* Asrc = ph ? g_agg : feat;
        const int gr = rowBase + fr;
        const bool valid = gr < NN;

        if (ph) __syncthreads();   // protect smem reuse from previous phase

        // ---- A fill: fp32 -> bf16 hi/lo into padded [128][AS] tiles ----
        #pragma unroll 4
        for (int j = 0; j < 16; j++) {
            int c = half * 64 + j * 4;
            float4 v = valid ? *(const float4*)(Asrc + (size_t)gr * FIN + c)
                             : make_float4(0.f, 0.f, 0.f, 0.f);
            __nv_bfloat16 hx = __float2bfloat16(v.x), hy = __float2bfloat16(v.y);
            __nv_bfloat16 hz = __float2bfloat16(v.z), hw = __float2bfloat16(v.w);
            __nv_bfloat16 lx = __float2bfloat16(v.x - __bfloat162float(hx));
            __nv_bfloat16 ly = __float2bfloat16(v.y - __bfloat162float(hy));
            __nv_bfloat16 lz = __float2bfloat16(v.z - __bfloat162float(hz));
            __nv_bfloat16 lw = __float2bfloat16(v.w - __bfloat162float(hw));
            uint32_t o = (uint32_t)((fr * AS + c) * 2);
            *(__nv_bfloat162*)(smem + SM_AHI + o)     = __halves2bfloat162(hx, hy);
            *(__nv_bfloat162*)(smem + SM_AHI + o + 4) = __halves2bfloat162(hz, hw);
            *(__nv_bfloat162*)(smem + SM_ALO + o)     = __halves2bfloat162(lx, ly);
            *(__nv_bfloat162*)(smem + SM_ALO + o + 4) = __halves2bfloat162(lz, lw);
        }
        __syncthreads();

        // ---- MMA mainloop: 8 k-steps of 16 ----
        #pragma unroll
        for (int ks = 0; ks < 8; ks++) {
            const int kb = ks * 16;
            // B fragments: 2x 64B contiguous per thread, L1/L2 resident
            uint32_t bhi[16], blo[16];
            {
                const uint4* hp = (const uint4*)&g_bf[ph][0][ks][wc][lane][0];
                const uint4* lp = (const uint4*)&g_bf[ph][1][ks][wc][lane][0];
                #pragma unroll
                for (int q = 0; q < 4; q++) {
                    *(uint4*)&bhi[q * 4] = hp[q];
                    *(uint4*)&blo[q * 4] = lp[q];
                }
            }
            uint32_t ahi[2][4], alo[2][4];
            #pragma unroll
            for (int mf = 0; mf < 2; mf++) {
                ldm_x4(ahi[mf], ldm_addr(sb + SM_AHI, wm + mf * 16, kb, lane));
                ldm_x4(alo[mf], ldm_addr(sb + SM_ALO, wm + mf * 16, kb, lane));
            }
            #pragma unroll
            for (int mf = 0; mf < 2; mf++)
                #pragma unroll
                for (int nf = 0; nf < 8; nf++) {
                    uint32_t bh0 = bhi[nf * 2], bh1 = bhi[nf * 2 + 1];
                    uint32_t bl0 = blo[nf * 2], bl1 = blo[nf * 2 + 1];
                    mma_bf16(acc[mf][nf], ahi[mf], bh0, bh1);
                    mma_bf16(acc[mf][nf], ahi[mf], bl0, bl1);
                    mma_bf16(acc[mf][nf], alo[mf], bh0, bh1);
                }
        }
    }

    // ---- epilogue: +bias, store ----
    const int wn = wc * 64;
    const int cg = (lane & 3) * 2;     // col pair within n-frag
    const int rr = lane >> 2;          // row within m-frag half
    #pragma unroll
    for (int mf = 0; mf < 2; mf++) {
        int r0 = rowBase + wm + mf * 16 + rr;
        int r1 = r0 + 8;
        #pragma unroll
        for (int nf = 0; nf < 8; nf++) {
            int col = wn + nf * 8 + cg;
            float b0 = __ldg(bself + col), b1 = __ldg(bself + col + 1);
            if (r0 < NN) {
                float2 o = make_float2(acc[mf][nf][0] + b0, acc[mf][nf][1] + b1);
                *(float2*)(out + (size_t)r0 * FIN + col) = o;
            }
            if (r1 < NN) {
                float2 o = make_float2(acc[mf][nf][2] + b0, acc[mf][nf][3] + b1);
                *(float2*)(out + (size_t)r1 * FIN + col) = o;
            }
        }
    }
}

// ---------------- launch ----------------
extern "C" void kernel_launch(void* const* d_in, const int* in_sizes, int n_in,
                              void* d_out, int out_size) {
    const float *feat = nullptr, *topkv = nullptr, *Wself = nullptr,
                *bself = nullptr, *Wneigh = nullptr;
    const int *topki = nullptr, *src = nullptr, *dst = nullptr;

    for (int i = 0; i < n_in; i++) {
        int s = in_sizes[i];
        const void* p = d_in[i];
        if (s == NN * FIN)       feat = (const float*)p;
        else if (s == NN * KK) { if (!topkv) topkv = (const float*)p; else topki = (const int*)p; }
        else if (s == EE)      { if (!src)   src   = (const int*)p;   else dst   = (const int*)p; }
        else if (s == 128*128) { if (!Wself) Wself = (const float*)p; else Wneigh = (const float*)p; }
        else if (s == 128)       bself = (const float*)p;
    }
    float* out = (float*)d_out;

    static void* p_deg = nullptr;
    static void* p_cur = nullptr;
    if (!p_deg) {
        cudaGetSymbolAddress(&p_deg, g_deg);
        cudaGetSymbolAddress(&p_cur, g_cur);
        cudaFuncSetAttribute(gemm_kernel, cudaFuncAttributeMaxDynamicSharedMemorySize, SM_TOTAL);
    }

    cudaMemsetAsync(p_deg, 0, NN * sizeof(int));
    cudaMemsetAsync(p_cur, 0, NN * sizeof(int));
    deg_kernel<<<(EE / 4 + 255) / 256, 256>>>(dst);
    scan1_kernel<<<NB_SCAN, 1024>>>();
    scan2_kernel<<<1, 32>>>();
    scatter_kernel<<<(EE / 4 + 255) / 256, 256>>>(src, dst);
    xs_kernel<<<(NN + 7) / 8, 256>>>(topkv, topki);
    wprep_kernel<<<128, 256>>>(Wself, Wneigh);
    agg_kernel<<<(NN + 7) / 8, 256>>>();
    gemm_kernel<<<(NN + 127) / 128, 256, SM_TOTAL>>>(feat, bself, out);
}